// round 2
// baseline (speedup 1.0000x reference)
#include <cuda_runtime.h>
#include <cuda_bf16.h>
#include <mma.h>
#include <math.h>

using namespace nvcuda;

// Problem constants
#define NN 50000
#define NE 800000
#define F  128
#define R  8
#define NKEY (NN * R)        // 400000 (dst,rel) buckets

// ---------------- device scratch (no cudaMalloc allowed) ----------------
__device__ float g_h1[(size_t)NN * F];   // layer-1 output
__device__ int   g_deg2[NKEY];
__device__ int   g_off2[NKEY + 1];
__device__ int   g_cur2[NKEY];
__device__ int   g_esrc[NE];             // src sorted by (dst, rel)
__device__ float g_pool[F];

// ---------------- CSR build (two-level: key = dst*8 + rel) ----------------
__global__ void k_zero() {
    int i = blockIdx.x * blockDim.x + threadIdx.x;
    if (i < NKEY) g_deg2[i] = 0;
    if (i < F)    g_pool[i] = 0.f;
}

__global__ void k_hist(const int* __restrict__ dst, const int* __restrict__ et) {
    int e = blockIdx.x * blockDim.x + threadIdx.x;
    if (e < NE) atomicAdd(&g_deg2[dst[e] * 8 + et[e]], 1);
}

// single-block exclusive scan over g_deg2 -> g_off2 / g_cur2
__global__ void k_scan() {
    __shared__ int warp_sums[32];
    const int TPB = 1024;
    int t = threadIdx.x;
    int chunk = (NKEY + TPB - 1) / TPB;        // 391
    int begin = t * chunk;
    int end = begin + chunk; if (end > NKEY) end = NKEY;
    int s = 0;
    for (int i = begin; i < end; i++) s += g_deg2[i];
    int lane = t & 31, wid = t >> 5;
    int v = s;
    #pragma unroll
    for (int o = 1; o < 32; o <<= 1) { int u = __shfl_up_sync(~0u, v, o); if (lane >= o) v += u; }
    if (lane == 31) warp_sums[wid] = v;
    __syncthreads();
    if (wid == 0) {
        int w = warp_sums[lane];
        #pragma unroll
        for (int o = 1; o < 32; o <<= 1) { int u = __shfl_up_sync(~0u, w, o); if (lane >= o) w += u; }
        warp_sums[lane] = w;
    }
    __syncthreads();
    int excl = v - s + (wid > 0 ? warp_sums[wid - 1] : 0);
    int run = excl;
    for (int i = begin; i < end; i++) {
        int d = g_deg2[i];
        g_off2[i] = run; g_cur2[i] = run;
        run += d;
    }
    if (t == TPB - 1) g_off2[NKEY] = run;
}

__global__ void k_scatter(const int* __restrict__ src, const int* __restrict__ dst,
                          const int* __restrict__ et) {
    int e = blockIdx.x * blockDim.x + threadIdx.x;
    if (e < NE) {
        int p = atomicAdd(&g_cur2[dst[e] * 8 + et[e]], 1);
        g_esrc[p] = src[e];
    }
}

// ---------------- fused agg + GEMM + epilogue ----------------
// One block = 128 dst nodes, 512 threads (16 warps, 4x4 warp grid for wmma).
// For kb in 0..7:  sT[n,:] = sum_{e in (n,kb)} h[src_e,:]  (register acc, write-once)
//                  C += sT @ W[kb]
// kb==8: self-loop: sT = h rows, C += sT @ Wself
// layer 0 epilogue: g_h1 = relu(C + b);  layer 1: fused mean-pool into g_pool.
#define FUSED_SMEM (2 * 128 * 132 * 4)

__global__ void __launch_bounds__(512)
k_fused(const float* __restrict__ hin_ext,
        const float* __restrict__ W,      // [8,128,128]
        const float* __restrict__ Wself,  // [128,128]
        const float* __restrict__ bias,   // [128]
        int layer) {
    extern __shared__ float sm[];
    float* sT = sm;                  // [128][132]
    float* sB = sm + 128 * 132;      // [128][132]
    const float* hin = (layer == 0) ? hin_ext : (const float*)g_h1;
    const float4* hin4 = (const float4*)hin;
    int m0 = blockIdx.x * 128;
    int t = threadIdx.x;
    int warp = t >> 5, lane = t & 31;
    int wm = warp >> 2;    // 4 tiles in M (32 rows each)
    int wn = warp & 3;     // 4 tiles in N (32 cols each)

    wmma::fragment<wmma::accumulator, 16, 16, 8, float> c[2][2];
    #pragma unroll
    for (int i = 0; i < 2; i++)
        #pragma unroll
        for (int j = 0; j < 2; j++) wmma::fill_fragment(c[i][j], 0.f);

    for (int kb = 0; kb < 9; kb++) {
        // ---- load B tile (concurrent with gather; latency hidden) ----
        const float4* Bb = (const float4*)((kb < 8) ? (W + (size_t)kb * 128 * 128) : Wself);
        #pragma unroll
        for (int i = 0; i < 8; i++) {
            int idx = t + i * 512;       // 0..4095 float4 slots
            int row = idx >> 5;
            int c4  = idx & 31;
            float4 v = Bb[row * 32 + c4];
            float* dp = sB + row * 132 + c4 * 4;
            dp[0] = wmma::__float_to_tf32(v.x);
            dp[1] = wmma::__float_to_tf32(v.y);
            dp[2] = wmma::__float_to_tf32(v.z);
            dp[3] = wmma::__float_to_tf32(v.w);
        }

        // ---- build sT tile: register accumulate, write exactly once ----
        if (kb < 8) {
            #pragma unroll
            for (int i = 0; i < 8; i++) {
                int nl = warp * 8 + i;           // 0..127
                int n = m0 + nl;
                float4 a = make_float4(0.f, 0.f, 0.f, 0.f);
                if (n < NN) {
                    int key = n * 8 + kb;
                    int e0 = g_off2[key], e1 = g_off2[key + 1];
                    int e = e0;
                    // 2x unroll for MLP
                    for (; e + 1 < e1; e += 2) {
                        int s0 = g_esrc[e], s1 = g_esrc[e + 1];
                        float4 v0 = hin4[(size_t)s0 * 32 + lane];
                        float4 v1 = hin4[(size_t)s1 * 32 + lane];
                        a.x += v0.x; a.y += v0.y; a.z += v0.z; a.w += v0.w;
                        a.x += v1.x; a.y += v1.y; a.z += v1.z; a.w += v1.w;
                    }
                    if (e < e1) {
                        int s0 = g_esrc[e];
                        float4 v0 = hin4[(size_t)s0 * 32 + lane];
                        a.x += v0.x; a.y += v0.y; a.z += v0.z; a.w += v0.w;
                    }
                }
                float* dp = sT + nl * 132 + lane * 4;
                dp[0] = wmma::__float_to_tf32(a.x);
                dp[1] = wmma::__float_to_tf32(a.y);
                dp[2] = wmma::__float_to_tf32(a.z);
                dp[3] = wmma::__float_to_tf32(a.w);
            }
        } else {
            // self-loop block: sT rows = hin rows
            #pragma unroll
            for (int i = 0; i < 8; i++) {
                int nl = warp * 8 + i;
                int n = m0 + nl;
                float4 a = (n < NN) ? hin4[(size_t)n * 32 + lane]
                                    : make_float4(0.f, 0.f, 0.f, 0.f);
                float* dp = sT + nl * 132 + lane * 4;
                dp[0] = wmma::__float_to_tf32(a.x);
                dp[1] = wmma::__float_to_tf32(a.y);
                dp[2] = wmma::__float_to_tf32(a.z);
                dp[3] = wmma::__float_to_tf32(a.w);
            }
        }
        __syncthreads();

        // ---- wmma accumulate ----
        #pragma unroll
        for (int ks = 0; ks < 16; ks++) {
            wmma::fragment<wmma::matrix_a, 16, 16, 8, wmma::precision::tf32, wmma::row_major> af[2];
            wmma::fragment<wmma::matrix_b, 16, 16, 8, wmma::precision::tf32, wmma::row_major> bf[2];
            #pragma unroll
            for (int i = 0; i < 2; i++)
                wmma::load_matrix_sync(af[i], sT + (wm * 32 + i * 16) * 132 + ks * 8, 132);
            #pragma unroll
            for (int j = 0; j < 2; j++)
                wmma::load_matrix_sync(bf[j], sB + (ks * 8) * 132 + wn * 32 + j * 16, 132);
            #pragma unroll
            for (int i = 0; i < 2; i++)
                #pragma unroll
                for (int j = 0; j < 2; j++)
                    wmma::mma_sync(c[i][j], af[i], bf[j], c[i][j]);
        }
        __syncthreads();
    }

    // ---- epilogue: dump C into sT ----
    #pragma unroll
    for (int i = 0; i < 2; i++)
        #pragma unroll
        for (int j = 0; j < 2; j++)
            wmma::store_matrix_sync(sT + (wm * 32 + i * 16) * 132 + wn * 32 + j * 16,
                                    c[i][j], 132, wmma::mem_row_major);
    __syncthreads();

    if (layer == 0) {
        const float4* b4 = (const float4*)bias;
        #pragma unroll
        for (int i = 0; i < 8; i++) {
            int idx = t + i * 512;
            int row = idx >> 5;
            int c4  = idx & 31;
            if (m0 + row < NN) {
                float4 bb = b4[c4];
                float* sp = sT + row * 132 + c4 * 4;
                float4 v;
                v.x = fmaxf(sp[0] + bb.x, 0.f);
                v.y = fmaxf(sp[1] + bb.y, 0.f);
                v.z = fmaxf(sp[2] + bb.z, 0.f);
                v.w = fmaxf(sp[3] + bb.w, 0.f);
                *(float4*)(g_h1 + (size_t)(m0 + row) * F + c4 * 4) = v;
            }
        }
    } else {
        // fused mean-pool: column sums over valid rows (4 row-groups of 32)
        int col = t & 127;
        int rg = t >> 7;            // 0..3
        float bc = bias[col];
        float s = 0.f;
        for (int r = rg * 32; r < rg * 32 + 32; r++) {
            if (m0 + r < NN) s += fmaxf(sT[r * 132 + col] + bc, 0.f);
        }
        atomicAdd(&g_pool[col], s);
    }
}

// ---------------- final: logits = mean-pool . fc_w + fc_b ; sigmoid ----------------
__global__ void k_final(const float* __restrict__ fc_w, const float* __restrict__ fc_b,
                        float* __restrict__ out) {
    __shared__ float red[F];
    int t = threadIdx.x;
    float v = g_pool[t] * (1.f / (float)NN) * fc_w[t];
    red[t] = v;
    __syncthreads();
    for (int o = 64; o > 0; o >>= 1) {
        if (t < o) red[t] += red[t + o];
        __syncthreads();
    }
    if (t == 0) {
        float logit = red[0] + fc_b[0];
        out[0] = 1.f / (1.f + expf(-logit));
    }
}

// ---------------- launch ----------------
extern "C" void kernel_launch(void* const* d_in, const int* in_sizes, int n_in,
                              void* d_out, int out_size) {
    const float* in_feat = (const float*)d_in[0];
    const float* W1   = (const float*)d_in[1];
    const float* W1s  = (const float*)d_in[2];
    const float* b1   = (const float*)d_in[3];
    const float* W2   = (const float*)d_in[4];
    const float* W2s  = (const float*)d_in[5];
    const float* b2   = (const float*)d_in[6];
    const float* fcw  = (const float*)d_in[7];
    const float* fcb  = (const float*)d_in[8];
    const int*   src  = (const int*)d_in[9];
    const int*   dst  = (const int*)d_in[10];
    const int*   et   = (const int*)d_in[11];
    float* out = (float*)d_out;

    cudaFuncSetAttribute(k_fused, cudaFuncAttributeMaxDynamicSharedMemorySize, FUSED_SMEM);

    k_zero<<<(NKEY + 511) / 512, 512>>>();
    k_hist<<<(NE + 255) / 256, 256>>>(dst, et);
    k_scan<<<1, 1024>>>();
    k_scatter<<<(NE + 255) / 256, 256>>>(src, dst, et);

    const int grid = (NN + 127) / 128;   // 391

    k_fused<<<grid, 512, FUSED_SMEM>>>(in_feat, W1, W1s, b1, 0);
    k_fused<<<grid, 512, FUSED_SMEM>>>(nullptr, W2, W2s, b2, 1);

    k_final<<<1, 128>>>(fcw, fcb, out);
}

// round 4
// speedup vs baseline: 1.3974x; 1.3974x over previous
#include <cuda_runtime.h>
#include <cuda_bf16.h>
#include <mma.h>
#include <math.h>
#include <cstdint>

using namespace nvcuda;

// Problem constants
#define NN 50000
#define NE 800000
#define F  128
#define R  8
#define NKEY (NN * R)        // 400000 (dst,rel) buckets

// GEMM tile config
#define PAD 144                       // bf16 elems per smem row (288B, 32B-aligned rows)
#define TB  (128 * PAD * 2)           // bytes per tile (36864)
#define GEMM_SMEM (4 * TB)            // A0 B0 A1 B1 = 147456

// ---------------- device scratch (no cudaMalloc allowed) ----------------
__device__ __nv_bfloat16 g_T[(size_t)NN * R * F];   // per-(node,rel) sums, bf16 [NKEY][128]
__device__ __nv_bfloat16 g_h1[(size_t)NN * F];      // layer-1 output (bf16)
__device__ __nv_bfloat16 g_hbf[(size_t)NN * F];     // bf16 copy of input features
__device__ __nv_bfloat16 g_Wb1[9 * F * F];          // W1 blocks 0..7 + W1_self (bf16)
__device__ __nv_bfloat16 g_Wb2[9 * F * F];          // W2 blocks 0..7 + W2_self (bf16)
__device__ int   g_deg2[NKEY];
__device__ int   g_off2[NKEY + 1];
__device__ int   g_cur2[NKEY];
__device__ int   g_esrc[NE];                        // src sorted by (dst, rel)
__device__ float g_pool[F];

// ---------------- cp.async helpers ----------------
__device__ __forceinline__ void cp_async16(void* sdst, const void* gsrc, int src_bytes) {
    unsigned s = (unsigned)__cvta_generic_to_shared(sdst);
    asm volatile("cp.async.cg.shared.global [%0], [%1], 16, %2;\n"
                 :: "r"(s), "l"(gsrc), "r"(src_bytes));
}
#define CP_COMMIT() asm volatile("cp.async.commit_group;\n" ::: "memory")
#define CP_WAIT(N)  asm volatile("cp.async.wait_group %0;\n" :: "n"(N) : "memory")

// ---------------- CSR build (two-level: key = dst*8 + rel) ----------------
__global__ void k_zero() {
    int i = blockIdx.x * blockDim.x + threadIdx.x;
    if (i < NKEY) g_deg2[i] = 0;
    if (i < F)    g_pool[i] = 0.f;
}

__global__ void k_hist(const int* __restrict__ dst, const int* __restrict__ et) {
    int e = blockIdx.x * blockDim.x + threadIdx.x;
    if (e < NE) atomicAdd(&g_deg2[dst[e] * 8 + et[e]], 1);
}

__global__ void k_scan() {
    __shared__ int warp_sums[32];
    const int TPB = 1024;
    int t = threadIdx.x;
    int chunk = (NKEY + TPB - 1) / TPB;        // 391
    int begin = t * chunk;
    int end = begin + chunk; if (end > NKEY) end = NKEY;
    int s = 0;
    for (int i = begin; i < end; i++) s += g_deg2[i];
    int lane = t & 31, wid = t >> 5;
    int v = s;
    #pragma unroll
    for (int o = 1; o < 32; o <<= 1) { int u = __shfl_up_sync(~0u, v, o); if (lane >= o) v += u; }
    if (lane == 31) warp_sums[wid] = v;
    __syncthreads();
    if (wid == 0) {
        int w = warp_sums[lane];
        #pragma unroll
        for (int o = 1; o < 32; o <<= 1) { int u = __shfl_up_sync(~0u, w, o); if (lane >= o) w += u; }
        warp_sums[lane] = w;
    }
    __syncthreads();
    int excl = v - s + (wid > 0 ? warp_sums[wid - 1] : 0);
    int run = excl;
    for (int i = begin; i < end; i++) {
        int d = g_deg2[i];
        g_off2[i] = run; g_cur2[i] = run;
        run += d;
    }
    if (t == TPB - 1) g_off2[NKEY] = run;
}

__global__ void k_scatter(const int* __restrict__ src, const int* __restrict__ dst,
                          const int* __restrict__ et) {
    int e = blockIdx.x * blockDim.x + threadIdx.x;
    if (e < NE) {
        int p = atomicAdd(&g_cur2[dst[e] * 8 + et[e]], 1);
        g_esrc[p] = src[e];
    }
}

// ---------------- fp32 -> bf16 converts ----------------
__global__ void k_cvt_in(const float* __restrict__ in_feat) {
    int i = blockIdx.x * blockDim.x + threadIdx.x;      // over NN*F/4
    if (i >= NN * F / 4) return;
    float4 v = ((const float4*)in_feat)[i];
    __nv_bfloat162 p0 = __floats2bfloat162_rn(v.x, v.y);
    __nv_bfloat162 p1 = __floats2bfloat162_rn(v.z, v.w);
    uint2 o; o.x = *(unsigned*)&p0; o.y = *(unsigned*)&p1;
    ((uint2*)g_hbf)[i] = o;
}

__global__ void k_cvt_w(const float* __restrict__ W, const float* __restrict__ Ws, int which) {
    int i = blockIdx.x * blockDim.x + threadIdx.x;      // over 9*F*F/4
    if (i >= 9 * F * F / 4) return;
    const float4* src = (i < 8 * F * F / 4) ? ((const float4*)W + i)
                                            : ((const float4*)Ws + (i - 8 * F * F / 4));
    float4 v = *src;
    __nv_bfloat162 p0 = __floats2bfloat162_rn(v.x, v.y);
    __nv_bfloat162 p1 = __floats2bfloat162_rn(v.z, v.w);
    uint2 o; o.x = *(unsigned*)&p0; o.y = *(unsigned*)&p1;
    ((uint2*)(which == 0 ? g_Wb1 : g_Wb2))[i] = o;
}

// ---------------- aggregation: one warp per (dst,rel) bucket ----------------
// g_T[key][0:128] = sum over bucket edges of hin[src]. Register-only, write-once.
__global__ void __launch_bounds__(256) k_agg(int layer) {
    int gid = (blockIdx.x * 256 + threadIdx.x) >> 5;
    int lane = threadIdx.x & 31;
    if (gid >= NKEY) return;
    const uint2* hin = (const uint2*)(layer ? g_h1 : g_hbf);   // bf16 rows, uint2 = 4 bf16/lane
    int e0 = g_off2[gid], e1 = g_off2[gid + 1];
    float a0 = 0.f, a1 = 0.f, a2 = 0.f, a3 = 0.f;
    for (int e = e0; e < e1; e++) {
        int s = g_esrc[e];
        uint2 raw = hin[(size_t)s * 32 + lane];
        __nv_bfloat162 p0 = *(__nv_bfloat162*)&raw.x;
        __nv_bfloat162 p1 = *(__nv_bfloat162*)&raw.y;
        float2 f0 = __bfloat1622float2(p0);
        float2 f1 = __bfloat1622float2(p1);
        a0 += f0.x; a1 += f0.y; a2 += f1.x; a3 += f1.y;
    }
    __nv_bfloat162 o0 = __floats2bfloat162_rn(a0, a1);
    __nv_bfloat162 o1 = __floats2bfloat162_rn(a2, a3);
    uint2 o; o.x = *(unsigned*)&o0; o.y = *(unsigned*)&o1;
    ((uint2*)g_T)[(size_t)gid * 32 + lane] = o;
}

// ---------------- GEMM: out = relu([T | hin] @ [W | Wself] + b), bf16 wmma, cp.async 2-stage ----
// 512 threads = 16 warps (4x4), warp tile 32x32, C tile 128x128, K = 9*128.
__global__ void __launch_bounds__(512)
k_gemm(const float* __restrict__ bias, int layer) {
    extern __shared__ char smraw[];
    const __nv_bfloat16* hin = layer ? g_h1 : g_hbf;
    const __nv_bfloat16* Wb  = layer ? g_Wb2 : g_Wb1;
    int m0 = blockIdx.x * 128;
    int t = threadIdx.x;
    int warp = t >> 5;
    int wm = warp >> 2;      // 0..3 (32-row tiles)
    int wn = warp & 3;       // 0..3 (32-col tiles)

    wmma::fragment<wmma::accumulator, 16, 16, 16, float> c[2][2];
    #pragma unroll
    for (int i = 0; i < 2; i++)
        #pragma unroll
        for (int j = 0; j < 2; j++) wmma::fill_fragment(c[i][j], 0.f);

    // tile loader: A rows from g_T (kb<8) or hin (kb==8); B from Wb
    auto load_tiles = [&](int stage, int kb) {
        char* sA = smraw + stage * 2 * TB;
        char* sB = sA + TB;
        #pragma unroll
        for (int i = 0; i < 4; i++) {
            int idx = t + i * 512;             // 0..2047
            int row = idx >> 4;
            int ch  = idx & 15;
            int gr = m0 + row;
            int vsz = 16;
            if (gr >= NN) { gr = 0; vsz = 0; }
            const char* src = (kb < 8)
                ? (const char*)(g_T + (size_t)gr * 1024 + kb * 128) + ch * 16
                : (const char*)(hin + (size_t)gr * 128) + ch * 16;
            cp_async16(sA + row * (PAD * 2) + ch * 16, src, vsz);
        }
        #pragma unroll
        for (int i = 0; i < 4; i++) {
            int idx = t + i * 512;
            int row = idx >> 4;
            int ch  = idx & 15;
            const char* src = (const char*)(Wb + (size_t)kb * F * F + row * 128) + ch * 16;
            cp_async16(sB + row * (PAD * 2) + ch * 16, src, 16);
        }
    };

    load_tiles(0, 0);
    CP_COMMIT();

    for (int kb = 0; kb < 9; kb++) {
        if (kb + 1 < 9) {
            load_tiles((kb + 1) & 1, kb + 1);
            CP_COMMIT();
            CP_WAIT(1);
        } else {
            CP_WAIT(0);
        }
        __syncthreads();

        const __nv_bfloat16* sA = (const __nv_bfloat16*)(smraw + (kb & 1) * 2 * TB);
        const __nv_bfloat16* sB = sA + 128 * PAD;
        #pragma unroll
        for (int ks = 0; ks < 8; ks++) {
            wmma::fragment<wmma::matrix_a, 16, 16, 16, __nv_bfloat16, wmma::row_major> af[2];
            wmma::fragment<wmma::matrix_b, 16, 16, 16, __nv_bfloat16, wmma::row_major> bf[2];
            #pragma unroll
            for (int i = 0; i < 2; i++)
                wmma::load_matrix_sync(af[i], sA + (wm * 32 + i * 16) * PAD + ks * 16, PAD);
            #pragma unroll
            for (int j = 0; j < 2; j++)
                wmma::load_matrix_sync(bf[j], sB + (ks * 16) * PAD + wn * 32 + j * 16, PAD);
            #pragma unroll
            for (int i = 0; i < 2; i++)
                #pragma unroll
                for (int j = 0; j < 2; j++)
                    wmma::mma_sync(c[i][j], af[i], bf[j], c[i][j]);
        }
        __syncthreads();
    }

    // epilogue: C -> smem fp32 [128][132]
    float* sC = (float*)smraw;
    #pragma unroll
    for (int i = 0; i < 2; i++)
        #pragma unroll
        for (int j = 0; j < 2; j++)
            wmma::store_matrix_sync(sC + (wm * 32 + i * 16) * 132 + wn * 32 + j * 16,
                                    c[i][j], 132, wmma::mem_row_major);
    __syncthreads();

    if (layer == 0) {
        #pragma unroll
        for (int i = 0; i < 8; i++) {
            int idx = t + i * 512;            // 0..4095 (row, 4-col group)
            int row = idx >> 5;
            int c4  = idx & 31;
            if (m0 + row < NN) {
                float* sp = sC + row * 132 + c4 * 4;
                float x = fmaxf(sp[0] + bias[c4 * 4 + 0], 0.f);
                float y = fmaxf(sp[1] + bias[c4 * 4 + 1], 0.f);
                float z = fmaxf(sp[2] + bias[c4 * 4 + 2], 0.f);
                float w = fmaxf(sp[3] + bias[c4 * 4 + 3], 0.f);
                __nv_bfloat162 p0 = __floats2bfloat162_rn(x, y);
                __nv_bfloat162 p1 = __floats2bfloat162_rn(z, w);
                uint2 o; o.x = *(unsigned*)&p0; o.y = *(unsigned*)&p1;
                ((uint2*)g_h1)[(size_t)(m0 + row) * 32 + c4] = o;
            }
        }
    } else {
        // fused mean-pool: column sums over valid rows (4 row-groups of 32)
        int col = t & 127;
        int rg = t >> 7;            // 0..3
        float bc = bias[col];
        float s = 0.f;
        for (int r = rg * 32; r < rg * 32 + 32; r++) {
            if (m0 + r < NN) s += fmaxf(sC[r * 132 + col] + bc, 0.f);
        }
        atomicAdd(&g_pool[col], s);
    }
}

// ---------------- final: logits = mean-pool . fc_w + fc_b ; sigmoid ----------------
__global__ void k_final(const float* __restrict__ fc_w, const float* __restrict__ fc_b,
                        float* __restrict__ out) {
    __shared__ float red[F];
    int t = threadIdx.x;
    red[t] = g_pool[t] * (1.f / (float)NN) * fc_w[t];
    __syncthreads();
    for (int o = 64; o > 0; o >>= 1) {
        if (t < o) red[t] += red[t + o];
        __syncthreads();
    }
    if (t == 0) {
        float logit = red[0] + fc_b[0];
        out[0] = 1.f / (1.f + expf(-logit));
    }
}

// ---------------- launch ----------------
extern "C" void kernel_launch(void* const* d_in, const int* in_sizes, int n_in,
                              void* d_out, int out_size) {
    const float* in_feat = (const float*)d_in[0];
    const float* W1   = (const float*)d_in[1];
    const float* W1s  = (const float*)d_in[2];
    const float* b1   = (const float*)d_in[3];
    const float* W2   = (const float*)d_in[4];
    const float* W2s  = (const float*)d_in[5];
    const float* b2   = (const float*)d_in[6];
    const float* fcw  = (const float*)d_in[7];
    const float* fcb  = (const float*)d_in[8];
    const int*   src  = (const int*)d_in[9];
    const int*   dst  = (const int*)d_in[10];
    const int*   et   = (const int*)d_in[11];
    float* out = (float*)d_out;

    cudaFuncSetAttribute(k_gemm, cudaFuncAttributeMaxDynamicSharedMemorySize, GEMM_SMEM);

    k_zero<<<(NKEY + 511) / 512, 512>>>();
    k_hist<<<(NE + 255) / 256, 256>>>(dst, et);
    k_scan<<<1, 1024>>>();
    k_scatter<<<(NE + 255) / 256, 256>>>(src, dst, et);
    k_cvt_in<<<(NN * F / 4 + 255) / 256, 256>>>(in_feat);
    k_cvt_w<<<(9 * F * F / 4 + 255) / 256, 256>>>(W1, W1s, 0);
    k_cvt_w<<<(9 * F * F / 4 + 255) / 256, 256>>>(W2, W2s, 1);

    const int grid = (NN + 127) / 128;   // 391

    k_agg<<<(NKEY + 7) / 8, 256>>>(0);
    k_gemm<<<grid, 512, GEMM_SMEM>>>(b1, 0);
    k_agg<<<(NKEY + 7) / 8, 256>>>(1);
    k_gemm<<<grid, 512, GEMM_SMEM>>>(b2, 1);

    k_final<<<1, 128>>>(fcw, fcb, out);
}

// round 5
// speedup vs baseline: 3.5798x; 2.5618x over previous
#include <cuda_runtime.h>
#include <cuda_bf16.h>
#include <mma.h>
#include <math.h>
#include <cstdint>

using namespace nvcuda;

// Problem constants
#define NN 50000
#define NE 800000
#define F  128
#define R  8
#define NKEY (NN * R)        // 400000 (dst,rel) buckets
#define NB  ((NKEY + 1023) / 1024)   // 391 scan blocks

// GEMM tile config
#define PAD 144                       // bf16 elems per smem row (288B, 32B-aligned rows)
#define TB  (128 * PAD * 2)           // bytes per tile (36864)
#define GEMM_SMEM (4 * TB)            // A0 B0 A1 B1 = 147456

// ---------------- device scratch (no cudaMalloc allowed) ----------------
__device__ __nv_bfloat16 g_T[(size_t)NN * R * F];   // per-(node,rel) sums, bf16 [NKEY][128]
__device__ __nv_bfloat16 g_h1[(size_t)NN * F];      // layer-1 output (bf16)
__device__ __nv_bfloat16 g_hbf[(size_t)NN * F];     // bf16 copy of input features
__device__ __nv_bfloat16 g_Wb1[9 * F * F];          // W1 blocks 0..7 + W1_self (bf16)
__device__ __nv_bfloat16 g_Wb2[9 * F * F];          // W2 blocks 0..7 + W2_self (bf16)
__device__ int   g_deg2[NKEY];
__device__ int   g_off2[NKEY + 1];
__device__ int   g_cur2[NKEY];
__device__ int   g_bsum[NB];
__device__ int   g_boff[NB];
__device__ int   g_esrc[NE];                        // src sorted by (dst, rel)
__device__ float g_pool[F];

// ---------------- cp.async helpers ----------------
__device__ __forceinline__ void cp_async16(void* sdst, const void* gsrc, int src_bytes) {
    unsigned s = (unsigned)__cvta_generic_to_shared(sdst);
    asm volatile("cp.async.cg.shared.global [%0], [%1], 16, %2;\n"
                 :: "r"(s), "l"(gsrc), "r"(src_bytes));
}
#define CP_COMMIT() asm volatile("cp.async.commit_group;\n" ::: "memory")
#define CP_WAIT(N)  asm volatile("cp.async.wait_group %0;\n" :: "n"(N) : "memory")

// ---------------- CSR build (two-level: key = dst*8 + rel) ----------------
__global__ void k_zero() {
    int i = blockIdx.x * blockDim.x + threadIdx.x;
    if (i < NKEY) g_deg2[i] = 0;
    if (i < F)    g_pool[i] = 0.f;
}

__global__ void k_hist(const int* __restrict__ dst, const int* __restrict__ et) {
    int e = blockIdx.x * blockDim.x + threadIdx.x;
    if (e < NE) atomicAdd(&g_deg2[dst[e] * 8 + et[e]], 1);
}

// ---- 3-kernel coalesced scan ----
// scan1: per-block sum of 1024 coalesced elements
__global__ void __launch_bounds__(1024) k_scan1() {
    __shared__ int ws[32];
    int b = blockIdx.x, t = threadIdx.x;
    int lane = t & 31, wid = t >> 5;
    int i = b * 1024 + t;
    int v = (i < NKEY) ? g_deg2[i] : 0;
    #pragma unroll
    for (int o = 16; o > 0; o >>= 1) v += __shfl_down_sync(~0u, v, o);
    if (lane == 0) ws[wid] = v;
    __syncthreads();
    if (wid == 0) {
        int s = ws[lane];
        #pragma unroll
        for (int o = 16; o > 0; o >>= 1) s += __shfl_down_sync(~0u, s, o);
        if (lane == 0) g_bsum[b] = s;
    }
}

// scan2: single block, exclusive scan of NB block sums
__global__ void __launch_bounds__(512) k_scan2() {
    __shared__ int ws[16];
    int t = threadIdx.x, lane = t & 31, wid = t >> 5;
    int v = (t < NB) ? g_bsum[t] : 0;
    int x = v;
    #pragma unroll
    for (int o = 1; o < 32; o <<= 1) { int u = __shfl_up_sync(~0u, x, o); if (lane >= o) x += u; }
    if (lane == 31) ws[wid] = x;
    __syncthreads();
    if (wid == 0 && lane < 16) {
        int s = ws[lane];
        #pragma unroll
        for (int o = 1; o < 16; o <<= 1) { int u = __shfl_up_sync(0xffffu, s, o); if (lane >= o) s += u; }
        ws[lane] = s;
    }
    __syncthreads();
    int excl = x - v + (wid > 0 ? ws[wid - 1] : 0);
    if (t < NB) g_boff[t] = excl;
    if (t == NB - 1) g_off2[NKEY] = excl + v;
}

// scan3: per-block exclusive scan + base, coalesced writes
__global__ void __launch_bounds__(1024) k_scan3() {
    __shared__ int ws[32];
    int b = blockIdx.x, t = threadIdx.x;
    int lane = t & 31, wid = t >> 5;
    int i = b * 1024 + t;
    int v = (i < NKEY) ? g_deg2[i] : 0;
    int x = v;
    #pragma unroll
    for (int o = 1; o < 32; o <<= 1) { int u = __shfl_up_sync(~0u, x, o); if (lane >= o) x += u; }
    if (lane == 31) ws[wid] = x;
    __syncthreads();
    if (wid == 0) {
        int s = ws[lane];
        #pragma unroll
        for (int o = 1; o < 32; o <<= 1) { int u = __shfl_up_sync(~0u, s, o); if (lane >= o) s += u; }
        ws[lane] = s;
    }
    __syncthreads();
    int excl = x - v + (wid > 0 ? ws[wid - 1] : 0) + g_boff[b];
    if (i < NKEY) { g_off2[i] = excl; g_cur2[i] = excl; }
}

__global__ void k_scatter(const int* __restrict__ src, const int* __restrict__ dst,
                          const int* __restrict__ et) {
    int e = blockIdx.x * blockDim.x + threadIdx.x;
    if (e < NE) {
        int p = atomicAdd(&g_cur2[dst[e] * 8 + et[e]], 1);
        g_esrc[p] = src[e];
    }
}

// ---------------- fp32 -> bf16 converts ----------------
__global__ void k_cvt_in(const float* __restrict__ in_feat) {
    int i = blockIdx.x * blockDim.x + threadIdx.x;      // over NN*F/4
    if (i >= NN * F / 4) return;
    float4 v = ((const float4*)in_feat)[i];
    __nv_bfloat162 p0 = __floats2bfloat162_rn(v.x, v.y);
    __nv_bfloat162 p1 = __floats2bfloat162_rn(v.z, v.w);
    uint2 o; o.x = *(unsigned*)&p0; o.y = *(unsigned*)&p1;
    ((uint2*)g_hbf)[i] = o;
}

__global__ void k_cvt_w(const float* __restrict__ W, const float* __restrict__ Ws, int which) {
    int i = blockIdx.x * blockDim.x + threadIdx.x;      // over 9*F*F/4
    if (i >= 9 * F * F / 4) return;
    const float4* src = (i < 8 * F * F / 4) ? ((const float4*)W + i)
                                            : ((const float4*)Ws + (i - 8 * F * F / 4));
    float4 v = *src;
    __nv_bfloat162 p0 = __floats2bfloat162_rn(v.x, v.y);
    __nv_bfloat162 p1 = __floats2bfloat162_rn(v.z, v.w);
    uint2 o; o.x = *(unsigned*)&p0; o.y = *(unsigned*)&p1;
    ((uint2*)(which == 0 ? g_Wb1 : g_Wb2))[i] = o;
}

// ---------------- aggregation: one warp per (dst,rel) bucket ----------------
__global__ void __launch_bounds__(256) k_agg(int layer) {
    int gid = (blockIdx.x * 256 + threadIdx.x) >> 5;
    int lane = threadIdx.x & 31;
    if (gid >= NKEY) return;
    const uint2* hin = (const uint2*)(layer ? g_h1 : g_hbf);
    int e0 = g_off2[gid], e1 = g_off2[gid + 1];
    float a0 = 0.f, a1 = 0.f, a2 = 0.f, a3 = 0.f;
    for (int e = e0; e < e1; e++) {
        int s = g_esrc[e];
        uint2 raw = hin[(size_t)s * 32 + lane];
        __nv_bfloat162 p0 = *(__nv_bfloat162*)&raw.x;
        __nv_bfloat162 p1 = *(__nv_bfloat162*)&raw.y;
        float2 f0 = __bfloat1622float2(p0);
        float2 f1 = __bfloat1622float2(p1);
        a0 += f0.x; a1 += f0.y; a2 += f1.x; a3 += f1.y;
    }
    __nv_bfloat162 o0 = __floats2bfloat162_rn(a0, a1);
    __nv_bfloat162 o1 = __floats2bfloat162_rn(a2, a3);
    uint2 o; o.x = *(unsigned*)&o0; o.y = *(unsigned*)&o1;
    ((uint2*)g_T)[(size_t)gid * 32 + lane] = o;
}

// ---------------- GEMM: out = relu([T | hin] @ [W | Wself] + b), bf16 wmma, cp.async 2-stage ----
__global__ void __launch_bounds__(512)
k_gemm(const float* __restrict__ bias, int layer) {
    extern __shared__ char smraw[];
    const __nv_bfloat16* hin = layer ? g_h1 : g_hbf;
    const __nv_bfloat16* Wb  = layer ? g_Wb2 : g_Wb1;
    int m0 = blockIdx.x * 128;
    int t = threadIdx.x;
    int warp = t >> 5;
    int wm = warp >> 2;
    int wn = warp & 3;

    wmma::fragment<wmma::accumulator, 16, 16, 16, float> c[2][2];
    #pragma unroll
    for (int i = 0; i < 2; i++)
        #pragma unroll
        for (int j = 0; j < 2; j++) wmma::fill_fragment(c[i][j], 0.f);

    auto load_tiles = [&](int stage, int kb) {
        char* sA = smraw + stage * 2 * TB;
        char* sB = sA + TB;
        #pragma unroll
        for (int i = 0; i < 4; i++) {
            int idx = t + i * 512;
            int row = idx >> 4;
            int ch  = idx & 15;
            int gr = m0 + row;
            int vsz = 16;
            if (gr >= NN) { gr = 0; vsz = 0; }
            const char* src = (kb < 8)
                ? (const char*)(g_T + (size_t)gr * 1024 + kb * 128) + ch * 16
                : (const char*)(hin + (size_t)gr * 128) + ch * 16;
            cp_async16(sA + row * (PAD * 2) + ch * 16, src, vsz);
        }
        #pragma unroll
        for (int i = 0; i < 4; i++) {
            int idx = t + i * 512;
            int row = idx >> 4;
            int ch  = idx & 15;
            const char* src = (const char*)(Wb + (size_t)kb * F * F + row * 128) + ch * 16;
            cp_async16(sB + row * (PAD * 2) + ch * 16, src, 16);
        }
    };

    load_tiles(0, 0);
    CP_COMMIT();

    for (int kb = 0; kb < 9; kb++) {
        if (kb + 1 < 9) {
            load_tiles((kb + 1) & 1, kb + 1);
            CP_COMMIT();
            CP_WAIT(1);
        } else {
            CP_WAIT(0);
        }
        __syncthreads();

        const __nv_bfloat16* sA = (const __nv_bfloat16*)(smraw + (kb & 1) * 2 * TB);
        const __nv_bfloat16* sB = sA + 128 * PAD;
        #pragma unroll
        for (int ks = 0; ks < 8; ks++) {
            wmma::fragment<wmma::matrix_a, 16, 16, 16, __nv_bfloat16, wmma::row_major> af[2];
            wmma::fragment<wmma::matrix_b, 16, 16, 16, __nv_bfloat16, wmma::row_major> bf[2];
            #pragma unroll
            for (int i = 0; i < 2; i++)
                wmma::load_matrix_sync(af[i], sA + (wm * 32 + i * 16) * PAD + ks * 16, PAD);
            #pragma unroll
            for (int j = 0; j < 2; j++)
                wmma::load_matrix_sync(bf[j], sB + (ks * 16) * PAD + wn * 32 + j * 16, PAD);
            #pragma unroll
            for (int i = 0; i < 2; i++)
                #pragma unroll
                for (int j = 0; j < 2; j++)
                    wmma::mma_sync(c[i][j], af[i], bf[j], c[i][j]);
        }
        __syncthreads();
    }

    float* sC = (float*)smraw;
    #pragma unroll
    for (int i = 0; i < 2; i++)
        #pragma unroll
        for (int j = 0; j < 2; j++)
            wmma::store_matrix_sync(sC + (wm * 32 + i * 16) * 132 + wn * 32 + j * 16,
                                    c[i][j], 132, wmma::mem_row_major);
    __syncthreads();

    if (layer == 0) {
        #pragma unroll
        for (int i = 0; i < 8; i++) {
            int idx = t + i * 512;
            int row = idx >> 5;
            int c4  = idx & 31;
            if (m0 + row < NN) {
                float* sp = sC + row * 132 + c4 * 4;
                float x = fmaxf(sp[0] + bias[c4 * 4 + 0], 0.f);
                float y = fmaxf(sp[1] + bias[c4 * 4 + 1], 0.f);
                float z = fmaxf(sp[2] + bias[c4 * 4 + 2], 0.f);
                float w = fmaxf(sp[3] + bias[c4 * 4 + 3], 0.f);
                __nv_bfloat162 p0 = __floats2bfloat162_rn(x, y);
                __nv_bfloat162 p1 = __floats2bfloat162_rn(z, w);
                uint2 o; o.x = *(unsigned*)&p0; o.y = *(unsigned*)&p1;
                ((uint2*)g_h1)[(size_t)(m0 + row) * 32 + c4] = o;
            }
        }
    } else {
        int col = t & 127;
        int rg = t >> 7;
        float bc = bias[col];
        float s = 0.f;
        for (int r = rg * 32; r < rg * 32 + 32; r++) {
            if (m0 + r < NN) s += fmaxf(sC[r * 132 + col] + bc, 0.f);
        }
        atomicAdd(&g_pool[col], s);
    }
}

// ---------------- final ----------------
__global__ void k_final(const float* __restrict__ fc_w, const float* __restrict__ fc_b,
                        float* __restrict__ out) {
    __shared__ float red[F];
    int t = threadIdx.x;
    red[t] = g_pool[t] * (1.f / (float)NN) * fc_w[t];
    __syncthreads();
    for (int o = 64; o > 0; o >>= 1) {
        if (t < o) red[t] += red[t + o];
        __syncthreads();
    }
    if (t == 0) {
        float logit = red[0] + fc_b[0];
        out[0] = 1.f / (1.f + expf(-logit));
    }
}

// ---------------- launch ----------------
extern "C" void kernel_launch(void* const* d_in, const int* in_sizes, int n_in,
                              void* d_out, int out_size) {
    const float* in_feat = (const float*)d_in[0];
    const float* W1   = (const float*)d_in[1];
    const float* W1s  = (const float*)d_in[2];
    const float* b1   = (const float*)d_in[3];
    const float* W2   = (const float*)d_in[4];
    const float* W2s  = (const float*)d_in[5];
    const float* b2   = (const float*)d_in[6];
    const float* fcw  = (const float*)d_in[7];
    const float* fcb  = (const float*)d_in[8];
    const int*   src  = (const int*)d_in[9];
    const int*   dst  = (const int*)d_in[10];
    const int*   et   = (const int*)d_in[11];
    float* out = (float*)d_out;

    cudaFuncSetAttribute(k_gemm, cudaFuncAttributeMaxDynamicSharedMemorySize, GEMM_SMEM);

    k_zero<<<(NKEY + 511) / 512, 512>>>();
    k_hist<<<(NE + 255) / 256, 256>>>(dst, et);
    k_scan1<<<NB, 1024>>>();
    k_scan2<<<1, 512>>>();
    k_scan3<<<NB, 1024>>>();
    k_scatter<<<(NE + 255) / 256, 256>>>(src, dst, et);
    k_cvt_in<<<(NN * F / 4 + 255) / 256, 256>>>(in_feat);
    k_cvt_w<<<(9 * F * F / 4 + 255) / 256, 256>>>(W1, W1s, 0);
    k_cvt_w<<<(9 * F * F / 4 + 255) / 256, 256>>>(W2, W2s, 1);

    const int grid = (NN + 127) / 128;   // 391

    k_agg<<<(NKEY + 7) / 8, 256>>>(0);
    k_gemm<<<grid, 512, GEMM_SMEM>>>(b1, 0);
    k_agg<<<(NKEY + 7) / 8, 256>>>(1);
    k_gemm<<<grid, 512, GEMM_SMEM>>>(b2, 1);

    k_final<<<1, 128>>>(fcw, fcb, out);
}